// round 15
// baseline (speedup 1.0000x reference)
#include <cuda_runtime.h>
#include <cstdint>

#define Bb 64
#define Hh 1024
#define Ss 512
#define THREADS 128
#define NCHUNK 16                  // s-chunks of 32 steps
#define QUARTERS 4                 // h split per producer chunk
#define TR_CTAS (Bb * NCHUNK * QUARTERS)   // 4096

#define T_TILE 8
#define NTILES (Ss / T_TILE)       // 64
#define SB_FLOATS (2 * T_TILE * Hh)                 // 16384 floats = 64 KB
#define SMEM_FLOATS (SB_FLOATS + (Ss + 8) + 64 + 8)
#define SMEM_BYTES (SMEM_FLOATS * 4)                // ~69.9 KB dynamic smem (scan only)

// Scratch: transposed seq [B][S][H]; norm partials [B][C][32][4]; flags [B*C].
__device__ float g_trans[(size_t)Bb * Ss * Hh];       // 128 MB
__device__ float g_ssp4[Bb * NCHUNK * 32 * QUARTERS]; // 512 KB
__device__ int   g_flag[Bb * NCHUNK];                 // target = QUARTERS; scan CTA resets

__device__ __forceinline__ void cpa16(uint32_t dst, const float* src) {
    asm volatile("cp.async.cg.shared.global [%0], [%1], 16;\n" :: "r"(dst), "l"(src));
}

__device__ __forceinline__ void wait_flag(int fi) {
    if (threadIdx.x == 0) {
        int v;
        asm volatile("ld.acquire.gpu.global.b32 %0, [%1];"
                     : "=r"(v) : "l"(g_flag + fi) : "memory");
        while (v < QUARTERS) {
            __nanosleep(64);
            asm volatile("ld.acquire.gpu.global.b32 %0, [%1];"
                         : "=r"(v) : "l"(g_flag + fi) : "memory");
        }
    }
    __syncthreads();
}

// ---------------------------------------------------------------------------
// Producer kernel: tiny static smem -> high occupancy, runs on a parallel
// graph branch. CTA (b, chunk, quarter): transpose 32s x 256h into g_trans
// + 4-way h-partial of ||s||^2, then release the per-(b,chunk) flag.
// ---------------------------------------------------------------------------
__global__ __launch_bounds__(THREADS, 1)
void producer_kernel(const float* __restrict__ seq) {
    __shared__ float tile[32][33];            // 4.2 KB
    const int tid  = threadIdx.x;
    const int lane = tid & 31;
    const int warp = tid >> 5;

    const int idx = blockIdx.x;               // chunk-major ordering
    const int q   = idx & 3;
    const int bc  = idx >> 2;                 // c*64 + b
    const int b   = bc & 63;
    const int c   = bc >> 6;
    const int s0  = c * 32;
    const int hq  = q * 256;

    const float* src = seq + (size_t)b * Hh * Ss;
    float* dst = g_trans + (size_t)b * Ss * Hh;

    float acc[8] = {0, 0, 0, 0, 0, 0, 0, 0};  // ssq partials, sl = warp + 4j
    for (int hb = 0; hb < 8; hb++) {
        const int h0 = hq + hb * 32;
#pragma unroll
        for (int j = 0; j < 8; j++) {
            int hr = warp + j * 4;
            tile[hr][lane] = src[(size_t)(h0 + hr) * Ss + s0 + lane];   // coalesced in s
        }
        __syncthreads();
#pragma unroll
        for (int j = 0; j < 8; j++) {
            int sl = warp + j * 4;
            float v = tile[lane][sl];                                   // pad-33: no conflicts
            dst[(size_t)(s0 + sl) * Hh + h0 + lane] = v;                // coalesced in h
            acc[j] = fmaf(v, v, acc[j]);
        }
        __syncthreads();                // tile reusable next hb
    }
    // One butterfly for all 8 sl partials (chains interleaved).
#pragma unroll
    for (int o = 16; o; o >>= 1) {
#pragma unroll
        for (int j = 0; j < 8; j++)
            acc[j] += __shfl_xor_sync(0xffffffffu, acc[j], o);
    }
    if (lane == 0) {
#pragma unroll
        for (int j = 0; j < 8; j++) {
            int sl = warp + 4 * j;
            g_ssp4[(b * NCHUNK + c) * 128 + sl * 4 + q] = acc[j];
        }
    }
    __syncthreads();
    if (tid == 0) {
        __threadfence();
        atomicAdd(&g_flag[b * NCHUNK + c], 1);
    }
}

// ---------------------------------------------------------------------------
// Scan kernel: one CTA per batch, 70 KB dynamic smem (R13-proven shape:
// T_TILE=8, double buffer, depth-1 cp.async pipeline).
// ---------------------------------------------------------------------------
__global__ __launch_bounds__(THREADS, 1)
void scan_kernel(const float* __restrict__ tree,
                 const float* __restrict__ mask_in,
                 float* __restrict__ out) {
    extern __shared__ float smf[];
    float* sbuf  = smf;                   // [2][T_TILE*Hh]  (64 KB)
    float* smask = smf + SB_FLOATS;       // [Ss+8]
    float* part  = smask + (Ss + 8);      // [2][32] : 16 float2 (dot,hh) per buffer

    const int tid  = threadIdx.x;
    const int lane = tid & 31;
    const int warp = tid >> 5;
    const int b = blockIdx.x;
    const uint32_t sb_u32 = (uint32_t)__cvta_generic_to_shared(sbuf);
    const float* gsrc = g_trans + (size_t)b * Ss * Hh;
    const float* ssp_b = g_ssp4 + b * NCHUNK * 128;

    for (int i = tid; i < Ss; i += THREADS) smask[i] = mask_in[b * Ss + i];
    if (tid < 8) smask[Ss + tid] = 0.0f;            // lookahead pad

    float h[8];
    {
        float4 a = *(const float4*)(tree + b * Hh + tid * 4);
        float4 c = *(const float4*)(tree + b * Hh + 512 + tid * 4);
        h[0]=a.x; h[1]=a.y; h[2]=a.z; h[3]=a.w;
        h[4]=c.x; h[5]=c.y; h[6]=c.z; h[7]=c.w;
    }

    // Chunk 0: wait, fetch norm partials (lane <-> s), prefetch tile 0 (8 steps).
    wait_flag(b * NCHUNK);
    float4 p4n = *(const float4*)(ssp_b + lane * 4);
    {
#pragma unroll
        for (int i = 0; i < 16; i++) {
            int c = tid + i * THREADS;               // 2048 x 16B chunks
            cpa16(sb_u32 + c * 16, gsrc + c * 4);
        }
        asm volatile("cp.async.commit_group;\n");
    }
    __syncthreads();     // smask visible

    int pp = 0;
    float rcur = 0.0f;                  // per-lane 1/||s|| for current chunk
    float mcur = smask[0], sinvcur = 0.0f;
    float4 s0, s1;

    for (int t = 0; t < Ss; t++) {
        const int sl = t & (T_TILE - 1);
        const int k  = t >> 3;
        if (sl == 0) {
            asm volatile("cp.async.wait_group 0;\n" ::: "memory");
            __syncthreads();                       // tile k visible; k-1 free
            const int nk = k + 1;
            if (nk < NTILES) {
                if ((nk & 3) == 0) {               // 8 steps before entering chunk cn
                    const int cn = nk >> 2;
                    wait_flag(b * NCHUNK + cn);
                    p4n = *(const float4*)(ssp_b + cn * 128 + lane * 4);
                }
                const float*   srcp = gsrc + (size_t)nk * T_TILE * Hh;
                const uint32_t d = sb_u32 + (uint32_t)((nk & 1) * T_TILE * Hh * 4);
#pragma unroll
                for (int i = 0; i < 16; i++) {
                    int c = tid + i * THREADS;
                    cpa16(d + c * 16, srcp + c * 4);
                }
                asm volatile("cp.async.commit_group;\n");
            }
            if ((k & 3) == 0) {                    // entering a chunk: consume p4n
                float ssq = (p4n.x + p4n.y) + (p4n.z + p4n.w);
                rcur = rsqrtf(fmaxf(ssq, 1e-30f));
                sinvcur = __shfl_sync(0xffffffffu, rcur, 0);   // s = 32c + 0
            }
            const float* sp = sbuf + (k & 1) * (T_TILE * Hh);
            s0 = *(const float4*)(sp + tid * 4);
            s1 = *(const float4*)(sp + 512 + tid * 4);
        }

        // One-step lookahead (LDS + SHFL latencies hidden under reductions).
        const float mnext    = smask[t + 1];
        const float sinvnext = __shfl_sync(0xffffffffu, rcur, (t + 1) & 31);
        const float* spn = sbuf + ((t >> 3) & 1) * (T_TILE * Hh) + (sl + 1) * Hh;

        if (mcur != 0.0f) {          // mask uniform across the block
            float sv[8] = {s0.x, s0.y, s0.z, s0.w, s1.x, s1.y, s1.z, s1.w};

            float d0 = 0.0f, d1 = 0.0f, q0 = 0.0f, q1 = 0.0f;
#pragma unroll
            for (int i = 0; i < 4; i++) {
                d0 = fmaf(h[i],     sv[i],     d0);
                d1 = fmaf(h[i + 4], sv[i + 4], d1);
                q0 = fmaf(h[i],     h[i],      q0);
                q1 = fmaf(h[i + 4], h[i + 4],  q1);
            }
            float dot = d0 + d1, hh = q0 + q1;
            // 3-level butterfly (chains interleaved): lanes 0-3 keep
            // 8-lane partial pairs.
#pragma unroll
            for (int o = 16; o >= 4; o >>= 1) {
                float td = __shfl_xor_sync(0xffffffffu, dot, o);
                float th = __shfl_xor_sync(0xffffffffu, hh,  o);
                dot += td;
                hh  += th;
            }

            // Prefetch next step's s BEFORE the barrier.
            if (sl != T_TILE - 1) {
                s0 = *(const float4*)(spn + tid * 4);
                s1 = *(const float4*)(spn + 512 + tid * 4);
            }

            // 16 lanes (0-3 of each warp) publish their partial pair.
            if (lane < 4)
                *(float2*)(part + pp * 32 + (warp * 4 + lane) * 2)
                    = make_float2(dot, hh);
            __syncthreads();
            // Every thread reads all 16 pairs (8 broadcast LDS.128) and
            // tree-sums them.
            const float4* pw = (const float4*)(part + pp * 32);
            float4 w0 = pw[0], w1 = pw[1], w2 = pw[2], w3 = pw[3];
            float4 w4 = pw[4], w5 = pw[5], w6 = pw[6], w7 = pw[7];
            float Da = (w0.x + w0.z) + (w1.x + w1.z);
            float Db = (w2.x + w2.z) + (w3.x + w3.z);
            float Dc = (w4.x + w4.z) + (w5.x + w5.z);
            float Dd = (w6.x + w6.z) + (w7.x + w7.z);
            float Ha = (w0.y + w0.w) + (w1.y + w1.w);
            float Hb = (w2.y + w2.w) + (w3.y + w3.w);
            float Hc = (w4.y + w4.w) + (w5.y + w5.w);
            float Hd = (w6.y + w6.w) + (w7.y + w7.w);
            float D  = (Da + Db) + (Dc + Dd);
            float HH = (Ha + Hb) + (Hc + Hd);

            float ra = rsqrtf(fmaxf(HH, 1e-30f));
            float a  = 1.0f - (D * ra) * sinvcur;  // h*(1-cos) + s; eps never binds
#pragma unroll
            for (int i = 0; i < 8; i++)
                h[i] = fminf(fmaxf(fmaf(h[i], a, sv[i]), -1.0f), 1.0f);
            pp ^= 1;
        } else {
            // reference clips even when mask == 0
#pragma unroll
            for (int i = 0; i < 8; i++)
                h[i] = fminf(fmaxf(h[i], -1.0f), 1.0f);
            if (sl != T_TILE - 1) {
                s0 = *(const float4*)(spn + tid * 4);
                s1 = *(const float4*)(spn + 512 + tid * 4);
            }
        }

        mcur    = mnext;
        sinvcur = sinvnext;
    }

    float* o = out + b * Hh;
    *(float4*)(o + tid * 4)       = make_float4(h[0], h[1], h[2], h[3]);
    *(float4*)(o + 512 + tid * 4) = make_float4(h[4], h[5], h[6], h[7]);

    // Reset this batch's flags for the next graph replay (all producer
    // atomicAdds for batch b happened-before flag==QUARTERS, which
    // happened-before this point). Graph replays are whole-graph serial,
    // so next replay's producers start after this.
    if (tid < NCHUNK) g_flag[b * NCHUNK + tid] = 0;
}

// ---------------------------------------------------------------------------
// Fork the producer onto a side stream so the graph holds two PARALLEL
// branches (producer: high-occupancy small-smem; scan: big-smem). Stream and
// events are lazily created host objects (no device memory), reused across
// calls; the fork/join event pattern is the documented way to capture
// multi-stream graphs.
// ---------------------------------------------------------------------------
extern "C" void kernel_launch(void* const* d_in, const int* in_sizes, int n_in,
                              void* d_out, int out_size) {
    const float* tree = (const float*)d_in[0];   // (B,H)
    const float* seq  = (const float*)d_in[1];   // (B,H,S)
    const float* mask = (const float*)d_in[2];   // (B,S)
    float* out = (float*)d_out;                  // (B,H)

    static cudaStream_t s2 = nullptr;
    static cudaEvent_t ev_fork = nullptr, ev_join = nullptr;
    if (s2 == nullptr) {
        cudaStreamCreateWithFlags(&s2, cudaStreamNonBlocking);
        cudaEventCreateWithFlags(&ev_fork, cudaEventDisableTiming);
        cudaEventCreateWithFlags(&ev_join, cudaEventDisableTiming);
        cudaFuncSetAttribute(scan_kernel,
                             cudaFuncAttributeMaxDynamicSharedMemorySize, SMEM_BYTES);
    }

    cudaEventRecord(ev_fork, 0);                 // fork from the capture stream
    cudaStreamWaitEvent(s2, ev_fork, 0);
    producer_kernel<<<TR_CTAS, THREADS, 0, s2>>>(seq);
    scan_kernel<<<Bb, THREADS, SMEM_BYTES>>>(tree, mask, out);
    cudaEventRecord(ev_join, s2);                // join the branch back
    cudaStreamWaitEvent((cudaStream_t)0, ev_join, 0);
}

// round 16
// speedup vs baseline: 2.6244x; 2.6244x over previous
#include <cuda_runtime.h>
#include <cstdint>

#define Bb 64
#define Hh 1024
#define Ss 512
#define THREADS 128
#define SCAN_CTAS Bb
#define NCHUNK 16                  // s-chunks of 32 steps
#define QUARTERS 4                 // h split per producer chunk
#define TR_CTAS (Bb * NCHUNK * QUARTERS)   // 4096

#define T_TILE 8
#define NTILES (Ss / T_TILE)       // 64
#define SB_FLOATS (2 * T_TILE * Hh)                 // 16384 floats = 64 KB
#define SMEM_FLOATS (SB_FLOATS + Ss + 64 + 8)
#define SMEM_BYTES (SMEM_FLOATS * 4)                // ~69.8 KB dynamic smem

// Scratch: transposed seq [B][S][H]; norm partials [B][C][32][4]; flags [B*C].
__device__ float g_trans[(size_t)Bb * Ss * Hh];       // 128 MB
__device__ float g_ssp4[Bb * NCHUNK * 32 * QUARTERS]; // 512 KB
__device__ int   g_flag[Bb * NCHUNK];                 // target = QUARTERS; scan CTA resets

__device__ __forceinline__ void cpa16(uint32_t dst, const float* src) {
    asm volatile("cp.async.cg.shared.global [%0], [%1], 16;\n" :: "r"(dst), "l"(src));
}

__device__ __forceinline__ void wait_flag(int fi) {
    if (threadIdx.x == 0) {
        int v;
        asm volatile("ld.acquire.gpu.global.b32 %0, [%1];"
                     : "=r"(v) : "l"(g_flag + fi) : "memory");
        while (v < QUARTERS) {
            __nanosleep(64);
            asm volatile("ld.acquire.gpu.global.b32 %0, [%1];"
                         : "=r"(v) : "l"(g_flag + fi) : "memory");
        }
    }
    __syncthreads();
}

// One scan step, SL a compile-time literal, fully branchless w.r.t. the mask:
//   h' = clip(h*(1 - cos*m) + s*m)   (exact for m in {0,1}; m=0 -> clip(h))
#define SCAN_STEP(SL)                                                           \
    do {                                                                        \
        float sv[8] = {s0.x, s0.y, s0.z, s0.w, s1.x, s1.y, s1.z, s1.w};         \
        float d0 = 0.f, d1 = 0.f, q0 = 0.f, q1 = 0.f;                           \
        _Pragma("unroll")                                                       \
        for (int i = 0; i < 4; i++) {                                           \
            d0 = fmaf(h[i],     sv[i],     d0);                                 \
            d1 = fmaf(h[i + 4], sv[i + 4], d1);                                 \
            q0 = fmaf(h[i],     h[i],      q0);                                 \
            q1 = fmaf(h[i + 4], h[i + 4],  q1);                                 \
        }                                                                       \
        float dot = d0 + d1, hh = q0 + q1;                                      \
        _Pragma("unroll")   /* 3 levels; lanes 0-3 keep 8-lane partials */      \
        for (int o = 16; o >= 4; o >>= 1) {                                     \
            float td = __shfl_xor_sync(0xffffffffu, dot, o);                    \
            float th = __shfl_xor_sync(0xffffffffu, hh,  o);                    \
            dot += td; hh += th;                                                \
        }                                                                       \
        /* off-critical-path while the butterfly is in flight: */               \
        const float m_ = mv[SL];                                                \
        float svm[8];                                                           \
        _Pragma("unroll")                                                       \
        for (int i = 0; i < 8; i++) svm[i] = sv[i] * m_;                        \
        if (SL != T_TILE - 1) {   /* compile-time: next-s prefetch */           \
            s0 = *(const float4*)(sp + (SL + 1) * Hh + tid * 4);                \
            s1 = *(const float4*)(sp + (SL + 1) * Hh + 512 + tid * 4);          \
        }                                                                       \
        if (lane < 4)                                                           \
            *(float2*)(part + pp * 32 + (warp * 4 + lane) * 2)                  \
                = make_float2(dot, hh);                                         \
        __syncthreads();                                                        \
        const float4* pw = (const float4*)(part + pp * 32);                     \
        float4 w0 = pw[0], w1 = pw[1], w2 = pw[2], w3 = pw[3];                  \
        float4 w4 = pw[4], w5 = pw[5], w6 = pw[6], w7 = pw[7];                  \
        float Da = (w0.x + w0.z) + (w1.x + w1.z);                               \
        float Db = (w2.x + w2.z) + (w3.x + w3.z);                               \
        float Dc = (w4.x + w4.z) + (w5.x + w5.z);                               \
        float Dd = (w6.x + w6.z) + (w7.x + w7.z);                               \
        float Ha = (w0.y + w0.w) + (w1.y + w1.w);                               \
        float Hb = (w2.y + w2.w) + (w3.y + w3.w);                               \
        float Hc = (w4.y + w4.w) + (w5.y + w5.w);                               \
        float Hd = (w6.y + w6.w) + (w7.y + w7.w);                               \
        float D  = (Da + Db) + (Dc + Dd);                                       \
        float HH = (Ha + Hb) + (Hc + Hd);                                       \
        float ra = rsqrtf(fmaxf(HH, 1e-30f));                                   \
        float a  = 1.0f - ((D * ra) * sinvv[SL]) * m_;  /* eps never binds */   \
        _Pragma("unroll")                                                       \
        for (int i = 0; i < 8; i++)                                             \
            h[i] = fminf(fmaxf(fmaf(h[i], a, svm[i]), -1.0f), 1.0f);            \
        pp ^= 1;                                                                \
    } while (0)

// ---------------------------------------------------------------------------
// bid 0..63 : scan CTA (batch b = bid);  bid 64.. : producer CTA (R13-proven).
// ---------------------------------------------------------------------------
__global__ __launch_bounds__(THREADS, 1)
void fused_kernel(const float* __restrict__ tree,
                  const float* __restrict__ seq,
                  const float* __restrict__ mask_in,
                  float* __restrict__ out) {
    extern __shared__ float smf[];
    const int tid  = threadIdx.x;
    const int lane = tid & 31;
    const int warp = tid >> 5;

    if (blockIdx.x >= SCAN_CTAS) {
        // ======================= producer role =======================
        float (*tile)[33] = (float(*)[33])smf;    // 32x33 floats (4.2 KB)
        const int idx = blockIdx.x - SCAN_CTAS;   // chunk-major ordering
        const int q   = idx & 3;
        const int bc  = idx >> 2;                 // c*64 + b
        const int b   = bc & 63;
        const int c   = bc >> 6;
        const int s0  = c * 32;
        const int hq  = q * 256;

        const float* src = seq + (size_t)b * Hh * Ss;
        float* dst = g_trans + (size_t)b * Ss * Hh;

        float acc[8] = {0, 0, 0, 0, 0, 0, 0, 0};  // ssq partials, sl = warp + 4j
        for (int hb = 0; hb < 8; hb++) {
            const int h0 = hq + hb * 32;
#pragma unroll
            for (int j = 0; j < 8; j++) {
                int hr = warp + j * 4;
                tile[hr][lane] = src[(size_t)(h0 + hr) * Ss + s0 + lane]; // coalesced in s
            }
            __syncthreads();
#pragma unroll
            for (int j = 0; j < 8; j++) {
                int sl = warp + j * 4;
                float v = tile[lane][sl];                                // pad-33: no conflicts
                dst[(size_t)(s0 + sl) * Hh + h0 + lane] = v;             // coalesced in h
                acc[j] = fmaf(v, v, acc[j]);
            }
            __syncthreads();            // tile reusable next hb
        }
#pragma unroll
        for (int o = 16; o; o >>= 1) {
#pragma unroll
            for (int j = 0; j < 8; j++)
                acc[j] += __shfl_xor_sync(0xffffffffu, acc[j], o);
        }
        if (lane == 0) {
#pragma unroll
            for (int j = 0; j < 8; j++) {
                int sl = warp + 4 * j;
                g_ssp4[(b * NCHUNK + c) * 128 + sl * 4 + q] = acc[j];
            }
        }
        __syncthreads();
        if (tid == 0) {
            __threadfence();
            atomicAdd(&g_flag[b * NCHUNK + c], 1);
        }
        return;
    }

    // ======================= scan role =======================
    float* sbuf  = smf;                   // [2][T_TILE*Hh]  (64 KB)
    float* smask = smf + SB_FLOATS;       // [Ss]
    float* part  = smask + Ss;            // [2][32] : 16 float2 (dot,hh) per buffer

    const int b = blockIdx.x;
    const uint32_t sb_u32 = (uint32_t)__cvta_generic_to_shared(sbuf);
    const float* gsrc = g_trans + (size_t)b * Ss * Hh;
    const float* ssp_b = g_ssp4 + b * NCHUNK * 128;

    for (int i = tid; i < Ss; i += THREADS) smask[i] = mask_in[b * Ss + i];

    float h[8];
    {
        float4 a = *(const float4*)(tree + b * Hh + tid * 4);
        float4 c = *(const float4*)(tree + b * Hh + 512 + tid * 4);
        h[0]=a.x; h[1]=a.y; h[2]=a.z; h[3]=a.w;
        h[4]=c.x; h[5]=c.y; h[6]=c.z; h[7]=c.w;
    }

    // Chunk 0: wait, fetch norm partials (lane <-> s), prefetch tile 0.
    wait_flag(b * NCHUNK);
    float4 p4n = *(const float4*)(ssp_b + lane * 4);
    {
#pragma unroll
        for (int i = 0; i < 16; i++) {
            int c = tid + i * THREADS;               // 2048 x 16B chunks
            cpa16(sb_u32 + c * 16, gsrc + c * 4);
        }
        asm volatile("cp.async.commit_group;\n");
    }
    __syncthreads();     // smask visible

    int pp = 0;
    float rcur = 0.0f;   // per-lane 1/||s|| for current chunk (lane <-> s)

    for (int k = 0; k < NTILES; k++) {
        asm volatile("cp.async.wait_group 0;\n" ::: "memory");
        __syncthreads();                           // tile k visible; k-1 free
        const int nk = k + 1;
        if (nk < NTILES) {
            if ((nk & 3) == 0) {                   // 8 steps before entering chunk cn
                const int cn = nk >> 2;
                wait_flag(b * NCHUNK + cn);
                p4n = *(const float4*)(ssp_b + cn * 128 + lane * 4);
            }
            const float*   srcp = gsrc + (size_t)nk * T_TILE * Hh;
            const uint32_t d = sb_u32 + (uint32_t)((nk & 1) * T_TILE * Hh * 4);
#pragma unroll
            for (int i = 0; i < 16; i++) {
                int c = tid + i * THREADS;
                cpa16(d + c * 16, srcp + c * 4);
            }
            asm volatile("cp.async.commit_group;\n");
        }
        if ((k & 3) == 0) {                        // entering a chunk: consume p4n
            float ssq = (p4n.x + p4n.y) + (p4n.z + p4n.w);
            rcur = rsqrtf(fmaxf(ssq, 1e-30f));
        }

        // Per-tile register arrays (filled off the critical path):
        const int base = (k & 3) * 8;              // s-offset within the chunk
        float sinvv[8];
#pragma unroll
        for (int j = 0; j < 8; j++)
            sinvv[j] = __shfl_sync(0xffffffffu, rcur, base + j);
        float4 ma = *(const float4*)(smask + k * 8);
        float4 mb = *(const float4*)(smask + k * 8 + 4);
        float mv[8] = {ma.x, ma.y, ma.z, ma.w, mb.x, mb.y, mb.z, mb.w};

        const float* sp = sbuf + (k & 1) * (T_TILE * Hh);
        float4 s0 = *(const float4*)(sp + tid * 4);
        float4 s1 = *(const float4*)(sp + 512 + tid * 4);

        SCAN_STEP(0); SCAN_STEP(1); SCAN_STEP(2); SCAN_STEP(3);
        SCAN_STEP(4); SCAN_STEP(5); SCAN_STEP(6); SCAN_STEP(7);
    }

    float* o = out + b * Hh;
    *(float4*)(o + tid * 4)       = make_float4(h[0], h[1], h[2], h[3]);
    *(float4*)(o + 512 + tid * 4) = make_float4(h[4], h[5], h[6], h[7]);

    // Reset this batch's flags for the next graph replay.
    if (tid < NCHUNK) g_flag[b * NCHUNK + tid] = 0;
}

// ---------------------------------------------------------------------------
extern "C" void kernel_launch(void* const* d_in, const int* in_sizes, int n_in,
                              void* d_out, int out_size) {
    const float* tree = (const float*)d_in[0];   // (B,H)
    const float* seq  = (const float*)d_in[1];   // (B,H,S)
    const float* mask = (const float*)d_in[2];   // (B,S)
    float* out = (float*)d_out;                  // (B,H)

    cudaFuncSetAttribute(fused_kernel,
                         cudaFuncAttributeMaxDynamicSharedMemorySize, SMEM_BYTES);
    fused_kernel<<<SCAN_CTAS + TR_CTAS, THREADS, SMEM_BYTES>>>(tree, seq, mask, out);
}